// round 14
// baseline (speedup 1.0000x reference)
#include <cuda_runtime.h>

#define CH      16
#define COUT    16
#define LN_EPS  1e-5f

typedef unsigned long long ull;

// ---- f32x2 packed helpers (sm_100+) ----
__device__ __forceinline__ ull pk2(float lo, float hi) {
    ull r; asm("mov.b64 %0, {%1, %2};" : "=l"(r) : "f"(lo), "f"(hi)); return r;
}
__device__ __forceinline__ void upk2(float& lo, float& hi, ull v) {
    asm("mov.b64 {%0, %1}, %2;" : "=f"(lo), "=f"(hi) : "l"(v));
}
__device__ __forceinline__ ull fma2(ull a, ull b, ull c) {
    ull d; asm("fma.rn.f32x2 %0, %1, %2, %3;" : "=l"(d) : "l"(a), "l"(b), "l"(c));
    return d;
}
__device__ __forceinline__ ull mul2(ull a, ull b) {
    ull d; asm("mul.rn.f32x2 %0, %1, %2;" : "=l"(d) : "l"(a), "l"(b));
    return d;
}

// ---------------------------------------------------------------------------
// Kernel 1: trivial zero-fill, one float4 per thread (measured ~7.2 TB/s).
// ---------------------------------------------------------------------------
__global__ void dvpn_zero_kernel(float4* __restrict__ out, long long n4) {
    long long i = (long long)blockIdx.x * blockDim.x + threadIdx.x;
    if (i < n4) out[i] = make_float4(0.f, 0.f, 0.f, 0.f);
}

// ---------------------------------------------------------------------------
// Kernel 2: compute + direct scatter. Thread = voxel; warp stages features
// coalesced into smem; packed f32x2 MLP1+LN1+relu; serial MLP2+LN2;
// write 64B cell at the voxel's true coord (zeros already laid down by K1).
// ---------------------------------------------------------------------------
__global__ __launch_bounds__(128) void dvpn_compute_kernel(
    const float* __restrict__ features,     // [V,32,4]
    const int*   __restrict__ num_points,   // [V]
    const int*   __restrict__ coords,       // [V,4]
    const float* __restrict__ W1, const float* __restrict__ b1,
    const float* __restrict__ g1, const float* __restrict__ be1,
    const float* __restrict__ W2, const float* __restrict__ b2,
    const float* __restrict__ g2, const float* __restrict__ be2,
    const int* __restrict__ pB, const int* __restrict__ pGH,
    const int* __restrict__ pGW, const int* __restrict__ pGZ,
    float* __restrict__ out,
    int V)
{
    __shared__ float4 sfeat[4][32 * 9];     // per-warp staging, stride 9 float4

    const int t = threadIdx.x;
    const int b = blockIdx.x;

    // ---- uniform params -> registers (pre-centered W1/b1: LN1 mean == 0) ----
    float w[4][16], b1c[16], g1s[16], be1s[16];
    #pragma unroll
    for (int i = 0; i < 4; i++) {
        #pragma unroll
        for (int q = 0; q < 4; q++) {
            float4 ww = __ldg(&((const float4*)W1)[i * 4 + q]);
            w[i][q*4+0] = ww.x; w[i][q*4+1] = ww.y;
            w[i][q*4+2] = ww.z; w[i][q*4+3] = ww.w;
        }
    }
    {
        float b1m = 0.f;
        #pragma unroll
        for (int q = 0; q < 4; q++) {
            float4 bb = __ldg(&((const float4*)b1)[q]);
            float4 gg = __ldg(&((const float4*)g1)[q]);
            float4 ee = __ldg(&((const float4*)be1)[q]);
            b1c[q*4+0]=bb.x; b1c[q*4+1]=bb.y; b1c[q*4+2]=bb.z; b1c[q*4+3]=bb.w;
            g1s[q*4+0]=gg.x; g1s[q*4+1]=gg.y; g1s[q*4+2]=gg.z; g1s[q*4+3]=gg.w;
            be1s[q*4+0]=ee.x; be1s[q*4+1]=ee.y; be1s[q*4+2]=ee.z; be1s[q*4+3]=ee.w;
            b1m += bb.x + bb.y + bb.z + bb.w;
        }
        b1m *= (1.f / CH);
        #pragma unroll
        for (int i = 0; i < 4; i++) {
            float m = 0.f;
            #pragma unroll
            for (int j = 0; j < CH; j++) m += w[i][j];
            m *= (1.f / CH);
            #pragma unroll
            for (int j = 0; j < CH; j++) w[i][j] -= m;
        }
        #pragma unroll
        for (int j = 0; j < CH; j++) b1c[j] -= b1m;
    }

    // pack to f32x2
    ull w1p[4][8], b1p[8], g1p[8], be1p[8];
    #pragma unroll
    for (int q = 0; q < 8; q++) {
        #pragma unroll
        for (int i = 0; i < 4; i++) w1p[i][q] = pk2(w[i][2*q], w[i][2*q+1]);
        b1p[q]  = pk2(b1c[2*q],  b1c[2*q+1]);
        g1p[q]  = pk2(g1s[2*q],  g1s[2*q+1]);
        be1p[q] = pk2(be1s[2*q], be1s[2*q+1]);
    }

    const int wv   = t >> 5;
    const int lane = t & 31;
    const int vbase = b * 128 + wv * 32;
    const int v     = vbase + lane;
    const int nvw   = min(32, V - vbase);
    const int n     = (v < V) ? num_points[v] : 0;

    const float4* f4 = (const float4*)features;

    float hacc[16];
    #pragma unroll
    for (int j = 0; j < CH; j++) hacc[j] = 0.f;

    if (nvw > 0) {
        #pragma unroll
        for (int c = 0; c < 4; c++) {
            __syncwarp();
            // stage 32 voxels x 8 points, coalesced
            #pragma unroll
            for (int k = 0; k < 8; k++) {
                const int idx = k * 32 + lane;
                const int j = idx >> 3, p = idx & 7;
                if (j < nvw)
                    sfeat[wv][j * 9 + p] =
                        f4[(long long)(vbase + j) * 32 + c * 8 + p];
            }
            __syncwarp();
            // compute 8 points (uniform loop, SEL-masked accumulate)
            #pragma unroll
            for (int pp = 0; pp < 8; pp++) {
                const int p = c * 8 + pp;
                float4 f = sfeat[wv][lane * 9 + pp];
                const ull fx = pk2(f.x, f.x), fy = pk2(f.y, f.y);
                const ull fz = pk2(f.z, f.z), fw = pk2(f.w, f.w);
                ull d2[8];
                #pragma unroll
                for (int q = 0; q < 8; q++) {
                    ull a = fma2(fx, w1p[0][q], b1p[q]);
                    a = fma2(fy, w1p[1][q], a);
                    a = fma2(fz, w1p[2][q], a);
                    d2[q] = fma2(fw, w1p[3][q], a);
                }
                ull vv = 0ULL;
                #pragma unroll
                for (int q = 0; q < 8; q++) vv = fma2(d2[q], d2[q], vv);
                float vlo, vhi; upk2(vlo, vhi, vv);
                const float r = rsqrtf(fmaf(vlo + vhi, 1.f / CH, LN_EPS));
                const ull rp = pk2(r, r);
                const bool on = (p < n);
                #pragma unroll
                for (int q = 0; q < 8; q++) {
                    ull tq = mul2(d2[q], rp);
                    tq = fma2(tq, g1p[q], be1p[q]);
                    float y0, y1; upk2(y0, y1, tq);
                    hacc[2*q]   += on ? fmaxf(y0, 0.f) : 0.f;
                    hacc[2*q+1] += on ? fmaxf(y1, 0.f) : 0.f;
                }
            }
        }
    }

    if (v >= V) return;

    // ---- MLP2 (serial scalar) ----
    float x[16];
    {
        const float fn = (float)n;
        #pragma unroll
        for (int q = 0; q < 4; q++) {
            float4 bb = __ldg(&((const float4*)b2)[q]);
            x[q*4+0] = fn*bb.x; x[q*4+1] = fn*bb.y;
            x[q*4+2] = fn*bb.z; x[q*4+3] = fn*bb.w;
        }
        #pragma unroll
        for (int k = 0; k < CH; k++) {
            const float hk = hacc[k];
            #pragma unroll
            for (int q = 0; q < 4; q++) {
                float4 ww = __ldg(&((const float4*)W2)[k * 4 + q]);
                x[q*4+0] = fmaf(hk, ww.x, x[q*4+0]);
                x[q*4+1] = fmaf(hk, ww.y, x[q*4+1]);
                x[q*4+2] = fmaf(hk, ww.z, x[q*4+2]);
                x[q*4+3] = fmaf(hk, ww.w, x[q*4+3]);
            }
        }
    }

    // ---- LN2 (serial) ----
    {
        float s = 0.f;
        #pragma unroll
        for (int o = 0; o < COUT; o++) s += x[o];
        const float mu = s * (1.f / COUT);
        float vs = 0.f;
        #pragma unroll
        for (int o = 0; o < COUT; o++) {
            const float dv = x[o] - mu;
            x[o] = dv;
            vs = fmaf(dv, dv, vs);
        }
        const float r2 = rsqrtf(fmaf(vs, 1.f / COUT, LN_EPS));
        #pragma unroll
        for (int q = 0; q < 4; q++) {
            float4 gg = __ldg(&((const float4*)g2)[q]);
            float4 ee = __ldg(&((const float4*)be2)[q]);
            x[q*4+0] = fmaf(x[q*4+0]*r2, gg.x, ee.x);
            x[q*4+1] = fmaf(x[q*4+1]*r2, gg.y, ee.y);
            x[q*4+2] = fmaf(x[q*4+2]*r2, gg.z, ee.z);
            x[q*4+3] = fmaf(x[q*4+3]*r2, gg.w, ee.w);
        }
    }

    // ---- direct scatter to the voxel's true cell (mode='drop' bounds) ----
    int4 c = ((const int4*)coords)[v];
    const int B = __ldg(pB), GH = __ldg(pGH), GW = __ldg(pGW), GZ = __ldg(pGZ);
    if (c.x >= 0 && c.x < B && c.y >= 0 && c.y < GH &&
        c.z >= 0 && c.z < GW && c.w >= 0 && c.w < GZ) {
        const long long cell =
            ((((long long)c.x * GH + c.y) * GW + c.z) * GZ + c.w);
        float4* cellp = (float4*)out + cell * 4;
        #pragma unroll
        for (int q = 0; q < 4; q++)
            cellp[q] = make_float4(x[q*4+0], x[q*4+1], x[q*4+2], x[q*4+3]);
    }
}

// ---------------------------------------------------------------------------
extern "C" void kernel_launch(void* const* d_in, const int* in_sizes, int n_in,
                              void* d_out, int out_size) {
    const float* features   = (const float*)d_in[0];
    const int*   num_points = (const int*)  d_in[1];
    const int*   coords     = (const int*)  d_in[2];
    const float* W1  = (const float*)d_in[3];
    const float* b1  = (const float*)d_in[4];
    const float* g1  = (const float*)d_in[5];
    const float* be1 = (const float*)d_in[6];
    const float* W2  = (const float*)d_in[7];
    const float* b2  = (const float*)d_in[8];
    const float* g2  = (const float*)d_in[9];
    const float* be2 = (const float*)d_in[10];
    const int*   pB  = (const int*)d_in[11];
    const int*   pGH = (const int*)d_in[12];
    const int*   pGW = (const int*)d_in[13];
    const int*   pGZ = (const int*)d_in[14];
    float* out = (float*)d_out;

    const int V = in_sizes[1];
    const long long n4 = (long long)out_size / 4;

    // K1: zero the grid (one float4 per thread)
    const long long zb = (n4 + 255) / 256;
    dvpn_zero_kernel<<<(int)zb, 256>>>((float4*)out, n4);

    // K2: compute + direct scatter
    const int cblocks = (V + 127) / 128;
    dvpn_compute_kernel<<<cblocks, 128>>>(
        features, num_points, coords,
        W1, b1, g1, be1, W2, b2, g2, be2,
        pB, pGH, pGW, pGZ, out, V);
}